// round 5
// baseline (speedup 1.0000x reference)
#include <cuda_runtime.h>

// AdaptiveFeaturePooling: 4-level ROIAlign (out=14, sr=2) + max over levels.
// R5: 3 graph nodes (was 4): memset(out) ; build (tables + dense mask array,
// no atomics/counter/reset) ; scatter (grid-strided scan of the mask array,
// valid cells spread one-per-block across the chip).

#define OUTSZ  14
#define CELLS  196
#define CH     256
#define GSAMP  28           // OUTSZ*2
#define MAXROI 512
#define CGRID  2048
#define NSCAN  ((MAXROI * CELLS + CGRID - 1) / CGRID)   // 49

// tab[r][l][a][j] = {w0, w1, lo(bits), hi(bits)}
__device__ float4 g_tab[MAXROI][4][2][GSAMP];
__device__ unsigned char g_mask[MAXROI * CELLS];

__global__ __launch_bounds__(256)
void afp_build(const float* __restrict__ rois)
{
    __shared__ float s_w0[4][2][GSAMP];
    __shared__ float s_w1[4][2][GSAMP];

    const int r   = blockIdx.x;
    const int tid = threadIdx.x;

    if (tid < 4 * 2 * GSAMP) {
        int l   = tid / (2 * GSAMP);
        int rem = tid - l * (2 * GSAMP);
        int a   = rem / GSAMP;           // 0=y, 1=x
        int j   = rem - a * GSAMP;

        float p1 = rois[r * 4 + (a == 0 ? 1 : 0)];
        float p2 = rois[r * 4 + (a == 0 ? 3 : 2)];
        #pragma unroll
        for (int i = 3; i >= 0; --i) {
            if (i >= l) {
                float s = (float)(28 << i);
                p1 = __fmul_rn(p1, s);
                p2 = __fmul_rn(p2, s);
            }
        }
        float len  = fmaxf(__fadd_rn(p2, -p1), 1.0f);
        float t    = __fdiv_rn(len, 14.0f);
        float step = ((float)j + 0.5f) * 0.5f;
        float c    = __fadd_rn(p1, __fmul_rn(step, t));

        int L = 224 >> l;
        bool valid = (c >= -1.0f) && (c <= (float)L);
        c = fminf(fmaxf(c, 0.0f), (float)(L - 1));
        float lo   = floorf(c);
        float frac = __fadd_rn(c, -lo);
        int loi = (int)lo;
        int hii = loi + 1;
        if (loi >= L - 1) { loi = L - 1; hii = L - 1; frac = 0.0f; }
        float v = valid ? 1.0f : 0.0f;
        float w0 = (1.0f - frac) * v;
        float w1 = frac * v;
        s_w0[l][a][j] = w0;
        s_w1[l][a][j] = w1;
        g_tab[r][l][a][j] = make_float4(w0, w1, __int_as_float(loi), __int_as_float(hii));
    }
    __syncthreads();

    if (tid < CELLS) {
        int py = tid / OUTSZ;
        int px = tid - py * OUTSZ;
        unsigned m = 0;
        #pragma unroll
        for (int l = 0; l < 4; ++l) {
            float wy = s_w0[l][0][2*py]   + s_w1[l][0][2*py]
                     + s_w0[l][0][2*py+1] + s_w1[l][0][2*py+1];
            float wx = s_w0[l][1][2*px]   + s_w1[l][1][2*px]
                     + s_w0[l][1][2*px+1] + s_w1[l][1][2*px+1];
            if (wy > 0.0f && wx > 0.0f) m |= (1u << l);
        }
        g_mask[r * CELLS + tid] = (unsigned char)m;
    }
}

__global__ __launch_bounds__(256)
void afp_scatter(const float* __restrict__ f0, const float* __restrict__ f1,
                 const float* __restrict__ f2, const float* __restrict__ f3,
                 float* __restrict__ out, int nent)
{
    __shared__ unsigned char s_m[NSCAN];

    const int b = blockIdx.x;
    const int tid = threadIdx.x;

    if (tid < NSCAN) {
        int e = b + tid * CGRID;
        s_m[tid] = (e < nent) ? g_mask[e] : (unsigned char)0;
    }
    __syncthreads();

    const int c = tid;                   // channel
    const float* fl[4] = { f0, f1, f2, f3 };

    #pragma unroll 1
    for (int k = 0; k < NSCAN; ++k) {
        unsigned m = s_m[k];
        if (!m) continue;
        int e    = b + k * CGRID;
        int r    = e / CELLS;
        int cell = e - r * CELLS;
        int py = cell / OUTSZ;
        int px = cell - py * OUTSZ;
        int sy = 2 * py, sx = 2 * px;

        float best = 0.0f;
        #pragma unroll
        for (int l = 0; l < 4; ++l) {
            if (m & (1u << l)) {
                int W = 224 >> l;
                const float* fc = fl[l] + (size_t)c * (W * W);
                float acc = 0.0f;
                #pragma unroll
                for (int dy = 0; dy < 2; ++dy) {
                    float4 ty = g_tab[r][l][0][sy + dy];     // broadcast
                    float wy0 = ty.x, wy1 = ty.y;
                    if (wy0 + wy1 > 0.0f) {
                        int y0 = __float_as_int(ty.z);
                        int y1 = __float_as_int(ty.w);
                        const float* row0 = fc + y0 * W;
                        const float* row1 = fc + y1 * W;
                        #pragma unroll
                        for (int dx = 0; dx < 2; ++dx) {
                            float4 tx = g_tab[r][l][1][sx + dx];
                            float wx0 = tx.x, wx1 = tx.y;
                            if (wx0 + wx1 > 0.0f) {
                                int x0 = __float_as_int(tx.z);
                                int x1 = __float_as_int(tx.w);
                                acc += wy0 * (wx0 * row0[x0] + wx1 * row0[x1])
                                     + wy1 * (wx0 * row1[x0] + wx1 * row1[x1]);
                            }
                        }
                    }
                }
                best = fmaxf(best, acc * 0.25f);
            }
        }
        out[(size_t)r * (CH * CELLS) + (size_t)c * CELLS + cell] = best;
    }
}

extern "C" void kernel_launch(void* const* d_in, const int* in_sizes, int n_in,
                              void* d_out, int out_size)
{
    const float* f0   = (const float*)d_in[0];
    const float* f1   = (const float*)d_in[1];
    const float* f2   = (const float*)d_in[2];
    const float* f3   = (const float*)d_in[3];
    const float* rois = (const float*)d_in[4];
    int R = in_sizes[4] / 4;

    cudaMemsetAsync(d_out, 0, (size_t)out_size * sizeof(float));
    afp_build<<<R, 256>>>(rois);
    afp_scatter<<<CGRID, 256>>>(f0, f1, f2, f3, (float*)d_out, R * CELLS);
}

// round 6
// speedup vs baseline: 1.1373x; 1.1373x over previous
#include <cuda_runtime.h>

// AdaptiveFeaturePooling: 4-level ROIAlign (out=14, sr=2) + max over levels.
// 3 graph nodes: memset(out) ; build (bilinear tables + compacted worklist of
// valid (roi,cell,mask) entries) ; scatter (one entry per block, 256 threads =
// 256 channels, 16 unconditional gathers per active level).
// The worklist counter self-resets at the end of scatter (ticket atomic), so
// no dedicated reset node is needed and the graph replays deterministically.

#define OUTSZ  14
#define CELLS  196
#define CH     256
#define GSAMP  28           // OUTSZ*2
#define MAXROI 512
#define CGRID  2048

// tab[r][l][a][j] = {w0, w1, lo(bits), hi(bits)}
__device__ float4 g_tab[MAXROI][4][2][GSAMP];
__device__ unsigned g_work[MAXROI * CELLS];   // (r<<12) | (cell<<4) | mask
__device__ int g_count;                        // starts 0, self-resets
__device__ int g_ticket;                       // starts 0, self-resets

__global__ __launch_bounds__(256)
void afp_build(const float* __restrict__ rois)
{
    __shared__ float s_w0[4][2][GSAMP];
    __shared__ float s_w1[4][2][GSAMP];

    const int r   = blockIdx.x;
    const int tid = threadIdx.x;

    // Bilinear prep, replicating reference fp32 op order exactly.
    if (tid < 4 * 2 * GSAMP) {
        int l   = tid / (2 * GSAMP);
        int rem = tid - l * (2 * GSAMP);
        int a   = rem / GSAMP;           // 0=y, 1=x
        int j   = rem - a * GSAMP;

        float p1 = rois[r * 4 + (a == 0 ? 1 : 0)];
        float p2 = rois[r * 4 + (a == 0 ? 3 : 2)];
        #pragma unroll
        for (int i = 3; i >= 0; --i) {
            if (i >= l) {
                float s = (float)(28 << i);
                p1 = __fmul_rn(p1, s);
                p2 = __fmul_rn(p2, s);
            }
        }
        float len  = fmaxf(__fadd_rn(p2, -p1), 1.0f);
        float t    = __fdiv_rn(len, 14.0f);
        float step = ((float)j + 0.5f) * 0.5f;
        float c    = __fadd_rn(p1, __fmul_rn(step, t));

        int L = 224 >> l;
        bool valid = (c >= -1.0f) && (c <= (float)L);
        c = fminf(fmaxf(c, 0.0f), (float)(L - 1));
        float lo   = floorf(c);
        float frac = __fadd_rn(c, -lo);
        int loi = (int)lo;
        int hii = loi + 1;
        if (loi >= L - 1) { loi = L - 1; hii = L - 1; frac = 0.0f; }
        float v  = valid ? 1.0f : 0.0f;
        float w0 = (1.0f - frac) * v;
        float w1 = frac * v;
        s_w0[l][a][j] = w0;
        s_w1[l][a][j] = w1;
        g_tab[r][l][a][j] = make_float4(w0, w1, __int_as_float(loi), __int_as_float(hii));
    }
    __syncthreads();

    // Compact (roi, cell, mask) entries for cells with any live level.
    if (tid < CELLS) {
        int py = tid / OUTSZ;
        int px = tid - py * OUTSZ;
        unsigned m = 0;
        #pragma unroll
        for (int l = 0; l < 4; ++l) {
            float wy = s_w0[l][0][2*py]   + s_w1[l][0][2*py]
                     + s_w0[l][0][2*py+1] + s_w1[l][0][2*py+1];
            float wx = s_w0[l][1][2*px]   + s_w1[l][1][2*px]
                     + s_w0[l][1][2*px+1] + s_w1[l][1][2*px+1];
            if (wy > 0.0f && wx > 0.0f) m |= (1u << l);
        }
        if (m) {
            int pos = atomicAdd(&g_count, 1);
            g_work[pos] = ((unsigned)r << 12) | ((unsigned)tid << 4) | m;
        }
    }
}

__global__ __launch_bounds__(256)
void afp_scatter(const float* __restrict__ f0, const float* __restrict__ f1,
                 const float* __restrict__ f2, const float* __restrict__ f3,
                 float* __restrict__ out)
{
    const int n = g_count;
    const int c = threadIdx.x;           // channel
    const float* fl[4] = { f0, f1, f2, f3 };

    for (int e = blockIdx.x; e < n; e += CGRID) {
        unsigned w = g_work[e];
        int r    = (int)(w >> 12);
        int cell = (int)((w >> 4) & 0xFF);
        unsigned m = w & 0xF;
        int py = cell / OUTSZ;
        int px = cell - py * OUTSZ;
        int sy = 2 * py, sx = 2 * px;

        float best = 0.0f;
        #pragma unroll
        for (int l = 0; l < 4; ++l) {
            if (m & (1u << l)) {
                const int W = 224 >> l;
                const float* fc = fl[l] + (size_t)c * (W * W);

                float4 ty0 = g_tab[r][l][0][sy];
                float4 ty1 = g_tab[r][l][0][sy + 1];
                float4 tx0 = g_tab[r][l][1][sx];
                float4 tx1 = g_tab[r][l][1][sx + 1];

                int ya0 = __float_as_int(ty0.z) * W, ya1 = __float_as_int(ty0.w) * W;
                int yb0 = __float_as_int(ty1.z) * W, yb1 = __float_as_int(ty1.w) * W;
                int xa0 = __float_as_int(tx0.z),     xa1 = __float_as_int(tx0.w);
                int xb0 = __float_as_int(tx1.z),     xb1 = __float_as_int(tx1.w);

                // 16 unconditional gathers (indices always clamped in-range;
                // zero weights kill invalid taps).
                float vaa0 = fc[ya0 + xa0], vaa1 = fc[ya0 + xa1];
                float vab0 = fc[ya0 + xb0], vab1 = fc[ya0 + xb1];
                float vba0 = fc[ya1 + xa0], vba1 = fc[ya1 + xa1];
                float vbb0 = fc[ya1 + xb0], vbb1 = fc[ya1 + xb1];
                float vca0 = fc[yb0 + xa0], vca1 = fc[yb0 + xa1];
                float vcb0 = fc[yb0 + xb0], vcb1 = fc[yb0 + xb1];
                float vda0 = fc[yb1 + xa0], vda1 = fc[yb1 + xa1];
                float vdb0 = fc[yb1 + xb0], vdb1 = fc[yb1 + xb1];

                float acc =
                    ty0.x * (tx0.x * vaa0 + tx0.y * vaa1) + ty0.y * (tx0.x * vba0 + tx0.y * vba1)
                  + ty0.x * (tx1.x * vab0 + tx1.y * vab1) + ty0.y * (tx1.x * vbb0 + tx1.y * vbb1)
                  + ty1.x * (tx0.x * vca0 + tx0.y * vca1) + ty1.y * (tx0.x * vda0 + tx0.y * vda1)
                  + ty1.x * (tx1.x * vcb0 + tx1.y * vcb1) + ty1.y * (tx1.x * vdb0 + tx1.y * vdb1);

                best = fmaxf(best, acc * 0.25f);
            }
        }
        out[(size_t)r * (CH * CELLS) + (size_t)c * CELLS + cell] = best;
    }

    // Self-reset for the next graph replay: last block to finish zeroes state.
    if (threadIdx.x == 0) {
        int t = atomicAdd(&g_ticket, 1);
        if (t == CGRID - 1) {
            g_count  = 0;
            g_ticket = 0;
        }
    }
}

extern "C" void kernel_launch(void* const* d_in, const int* in_sizes, int n_in,
                              void* d_out, int out_size)
{
    const float* f0   = (const float*)d_in[0];
    const float* f1   = (const float*)d_in[1];
    const float* f2   = (const float*)d_in[2];
    const float* f3   = (const float*)d_in[3];
    const float* rois = (const float*)d_in[4];
    int R = in_sizes[4] / 4;

    cudaMemsetAsync(d_out, 0, (size_t)out_size * sizeof(float));
    afp_build<<<R, 256>>>(rois);
    afp_scatter<<<CGRID, 256>>>(f0, f1, f2, f3, (float*)d_out);
}

// round 7
// speedup vs baseline: 1.2709x; 1.1175x over previous
#include <cuda_runtime.h>

// AdaptiveFeaturePooling: 4-level ROIAlign (out=14, sr=2) + max over levels.
// Nodes: memset(out) ; build (tables + compacted worklist) ; scatter.
// Scatter lane remap: thread = (channel_quarter, x_tap). The 4 x-taps of a row
// share a 32B sector, so each warp-gather touches 8 L1 lines instead of 32
// (4x fewer wavefronts than thread=channel). Butterfly-shuffle over the 4-lane
// group completes the bilinear sum; lane 0 stores the channel result.

#define OUTSZ  14
#define CELLS  196
#define CH     256
#define GSAMP  28           // OUTSZ*2
#define MAXROI 512
#define CGRID  2048

// tab[r][l][a][j] = {w0, w1, lo(bits), hi(bits)}
__device__ float4 g_tab[MAXROI][4][2][GSAMP];
__device__ unsigned g_work[MAXROI * CELLS];   // (r<<12) | (cell<<4) | mask
__device__ int g_count;                        // starts 0, self-resets
__device__ int g_ticket;                       // starts 0, self-resets

__global__ __launch_bounds__(256)
void afp_build(const float* __restrict__ rois)
{
    __shared__ float s_w0[4][2][GSAMP];
    __shared__ float s_w1[4][2][GSAMP];

    const int r   = blockIdx.x;
    const int tid = threadIdx.x;

    // Bilinear prep, replicating reference fp32 op order exactly.
    if (tid < 4 * 2 * GSAMP) {
        int l   = tid / (2 * GSAMP);
        int rem = tid - l * (2 * GSAMP);
        int a   = rem / GSAMP;           // 0=y, 1=x
        int j   = rem - a * GSAMP;

        float p1 = rois[r * 4 + (a == 0 ? 1 : 0)];
        float p2 = rois[r * 4 + (a == 0 ? 3 : 2)];
        #pragma unroll
        for (int i = 3; i >= 0; --i) {
            if (i >= l) {
                float s = (float)(28 << i);
                p1 = __fmul_rn(p1, s);
                p2 = __fmul_rn(p2, s);
            }
        }
        float len  = fmaxf(__fadd_rn(p2, -p1), 1.0f);
        float t    = __fdiv_rn(len, 14.0f);
        float step = ((float)j + 0.5f) * 0.5f;
        float c    = __fadd_rn(p1, __fmul_rn(step, t));

        int L = 224 >> l;
        bool valid = (c >= -1.0f) && (c <= (float)L);
        c = fminf(fmaxf(c, 0.0f), (float)(L - 1));
        float lo   = floorf(c);
        float frac = __fadd_rn(c, -lo);
        int loi = (int)lo;
        int hii = loi + 1;
        if (loi >= L - 1) { loi = L - 1; hii = L - 1; frac = 0.0f; }
        float v  = valid ? 1.0f : 0.0f;
        float w0 = (1.0f - frac) * v;
        float w1 = frac * v;
        s_w0[l][a][j] = w0;
        s_w1[l][a][j] = w1;
        g_tab[r][l][a][j] = make_float4(w0, w1, __int_as_float(loi), __int_as_float(hii));
    }
    __syncthreads();

    // Compact (roi, cell, mask) entries for cells with any live level.
    if (tid < CELLS) {
        int py = tid / OUTSZ;
        int px = tid - py * OUTSZ;
        unsigned m = 0;
        #pragma unroll
        for (int l = 0; l < 4; ++l) {
            float wy = s_w0[l][0][2*py]   + s_w1[l][0][2*py]
                     + s_w0[l][0][2*py+1] + s_w1[l][0][2*py+1];
            float wx = s_w0[l][1][2*px]   + s_w1[l][1][2*px]
                     + s_w0[l][1][2*px+1] + s_w1[l][1][2*px+1];
            if (wy > 0.0f && wx > 0.0f) m |= (1u << l);
        }
        if (m) {
            int pos = atomicAdd(&g_count, 1);
            g_work[pos] = ((unsigned)r << 12) | ((unsigned)tid << 4) | m;
        }
    }
}

__global__ __launch_bounds__(256)
void afp_scatter(const float* __restrict__ f0, const float* __restrict__ f1,
                 const float* __restrict__ f2, const float* __restrict__ f3,
                 float* __restrict__ out)
{
    const int n   = g_count;
    const int tid = threadIdx.x;
    const int xi  = tid & 3;             // x-tap lane within 4-lane group
    const int cq  = tid >> 2;            // channel quarter index 0..63
    const float* fl[4] = { f0, f1, f2, f3 };

    for (int e = blockIdx.x; e < n; e += CGRID) {
        unsigned w = g_work[e];
        int r    = (int)(w >> 12);
        int cell = (int)((w >> 4) & 0xFF);
        unsigned m = w & 0xF;
        int py = cell / OUTSZ;
        int px = cell - py * OUTSZ;
        int sy = 2 * py, sx = 2 * px;

        const size_t obase = (size_t)r * (CH * CELLS) + cell;

        #pragma unroll
        for (int p = 0; p < 4; ++p) {
            const int c = cq + 64 * p;   // this group's channel
            float best = 0.0f;

            #pragma unroll
            for (int l = 0; l < 4; ++l) {
                if (m & (1u << l)) {
                    const int W = 224 >> l;
                    const float* fc = fl[l] + (size_t)c * (W * W);

                    float4 ty0 = g_tab[r][l][0][sy];
                    float4 ty1 = g_tab[r][l][0][sy + 1];
                    float4 tx0 = g_tab[r][l][1][sx];
                    float4 tx1 = g_tab[r][l][1][sx + 1];

                    // this lane's x-tap (weight + column)
                    float wx; int x;
                    if (xi == 0)      { wx = tx0.x; x = __float_as_int(tx0.z); }
                    else if (xi == 1) { wx = tx0.y; x = __float_as_int(tx0.w); }
                    else if (xi == 2) { wx = tx1.x; x = __float_as_int(tx1.z); }
                    else              { wx = tx1.y; x = __float_as_int(tx1.w); }

                    int y0 = __float_as_int(ty0.z) * W;
                    int y1 = __float_as_int(ty0.w) * W;
                    int y2 = __float_as_int(ty1.z) * W;
                    int y3 = __float_as_int(ty1.w) * W;

                    // 4 gathers per thread; warp touches 8 lines per LDG
                    float v0 = fc[y0 + x];
                    float v1 = fc[y1 + x];
                    float v2 = fc[y2 + x];
                    float v3 = fc[y3 + x];

                    float acc = wx * (ty0.x * v0 + ty0.y * v1
                                    + ty1.x * v2 + ty1.y * v3);
                    acc += __shfl_xor_sync(0xFFFFFFFFu, acc, 1);
                    acc += __shfl_xor_sync(0xFFFFFFFFu, acc, 2);

                    best = fmaxf(best, acc * 0.25f);
                }
            }
            if (xi == 0)
                out[obase + (size_t)c * CELLS] = best;
        }
    }

    // Self-reset for the next graph replay: last block to finish zeroes state.
    if (tid == 0) {
        int t = atomicAdd(&g_ticket, 1);
        if (t == CGRID - 1) {
            g_count  = 0;
            g_ticket = 0;
        }
    }
}

extern "C" void kernel_launch(void* const* d_in, const int* in_sizes, int n_in,
                              void* d_out, int out_size)
{
    const float* f0   = (const float*)d_in[0];
    const float* f1   = (const float*)d_in[1];
    const float* f2   = (const float*)d_in[2];
    const float* f3   = (const float*)d_in[3];
    const float* rois = (const float*)d_in[4];
    int R = in_sizes[4] / 4;

    cudaMemsetAsync(d_out, 0, (size_t)out_size * sizeof(float));
    afp_build<<<R, 256>>>(rois);
    afp_scatter<<<CGRID, 256>>>(f0, f1, f2, f3, (float*)d_out);
}